// round 11
// baseline (speedup 1.0000x reference)
#include <cuda_runtime.h>
#include <math.h>

// ---------------- problem constants ----------------
#define Bv   2
#define Cch  256
#define Nn   32768           // D*H*W
#define Ss   256
#define TDd  512
#define NH   8
#define HD   32
#define SCALE 0.17677669529663687f   // 32^-0.5
#define ASLICE 18             // persistent attn CTAs per (b,h)

// ---------------- scratch ----------------
__device__ float g_krot[Bv * NH * Ss * HD];          // [b,h,s,hd]
__device__ float g_v   [Bv * NH * Ss * HD];          // [b,h,s,hd]
__device__ float g_qrot[(size_t)Bv * NH * Nn * HD];  // [b,h,n,hd]  64MB
__device__ float g_att [(size_t)Bv * Nn * Cch];      // [b,n,c]     64MB

// ---------------- helpers ----------------
__device__ __forceinline__ unsigned f2tf(float x) {
    unsigned u;
    asm("cvt.rna.tf32.f32 %0, %1;" : "=r"(u) : "f"(x));
    return u;
}
__device__ __forceinline__ float tfval(float x) { return __uint_as_float(f2tf(x)); }

__device__ __forceinline__ void mma8(float c[4], const unsigned a[4],
                                     unsigned b0, unsigned b1) {
    asm volatile(
        "mma.sync.aligned.m16n8k8.row.col.f32.tf32.tf32.f32 "
        "{%0,%1,%2,%3},{%4,%5,%6,%7},{%8,%9},{%0,%1,%2,%3};"
        : "+f"(c[0]), "+f"(c[1]), "+f"(c[2]), "+f"(c[3])
        : "r"(a[0]), "r"(a[1]), "r"(a[2]), "r"(a[3]), "r"(b0), "r"(b1));
}

__device__ __forceinline__ void cpasync16(unsigned dst, const void* src) {
    asm volatile("cp.async.ca.shared.global [%0], [%1], 16;" :: "r"(dst), "l"(src));
}
#define CP_COMMIT()  asm volatile("cp.async.commit_group;")
#define CP_WAIT(n)   asm volatile("cp.async.wait_group %0;" :: "n"(n))

// ---------------------------------------------------------------------------
// Kernel 1: text side (K/V proj, MLP phase, rope on K). 64 CTAs, tiny. FFMA.
// ---------------------------------------------------------------------------
__global__ void text_kernel(const float* __restrict__ text,
                            const float* __restrict__ k_w, const float* __restrict__ k_b,
                            const float* __restrict__ v_w, const float* __restrict__ v_b,
                            const float* __restrict__ m1_w, const float* __restrict__ m1_b,
                            const float* __restrict__ m2_w, const float* __restrict__ m2_b)
{
    __shared__ float t_s[8][TDd];
    __shared__ float h_s[8][Cch];
    __shared__ float k_s[8][Cch];

    const int tid  = threadIdx.x;
    const int row0 = blockIdx.x * 8;

    #pragma unroll
    for (int r = 0; r < 8; r++) {
        t_s[r][tid]       = text[(size_t)(row0 + r) * TDd + tid];
        t_s[r][tid + 256] = text[(size_t)(row0 + r) * TDd + tid + 256];
    }
    __syncthreads();

    float ka[8], va[8], ha[8];
    #pragma unroll
    for (int r = 0; r < 8; r++) { ka[r] = k_b[tid]; va[r] = v_b[tid]; ha[r] = m1_b[tid]; }

    for (int i = 0; i < TDd; i++) {
        const float wk = k_w[i * Cch + tid];
        const float wv = v_w[i * Cch + tid];
        const float wm = m1_w[i * Cch + tid];
        #pragma unroll
        for (int r = 0; r < 8; r++) {
            const float t = t_s[r][i];
            ka[r] += t * wk;  va[r] += t * wv;  ha[r] += t * wm;
        }
    }

    #pragma unroll
    for (int r = 0; r < 8; r++) {
        const float x = ha[r];
        h_s[r][tid] = 0.5f * x * (1.0f + erff(x * 0.7071067811865475f));
        k_s[r][tid] = ka[r];
    }
    __syncthreads();

    float pa[8];
    #pragma unroll
    for (int r = 0; r < 8; r++) pa[r] = m2_b[tid];
    for (int i = 0; i < Cch; i++) {
        const float wm2 = m2_w[i * Cch + tid];
        #pragma unroll
        for (int r = 0; r < 8; r++) pa[r] += h_s[r][i] * wm2;
    }

    const int j    = tid & 31;
    const int head = tid >> 5;
    const int part = (j < 16) ? tid + 16 : tid - 16;
    const float sgn = (j < 16) ? -1.0f : 1.0f;

    #pragma unroll
    for (int r = 0; r < 8; r++) {
        const int row = row0 + r;
        const int b = row >> 8;
        const int s = row & 255;
        float sf, cf;
        sincosf(pa[r], &sf, &cf);
        const float krot = k_s[r][tid] * cf + sgn * k_s[r][part] * sf;
        const int o = ((b * NH + head) * Ss + s) * HD + j;
        g_krot[o] = krot;
        g_v[o]    = va[r];
    }
}

// ---------------------------------------------------------------------------
// Projection kernels: TF32 mma, cp.async double-buffered staging.
// ---------------------------------------------------------------------------
#define QA0  0
#define QA1  2304            // 32*72
#define QW0  4608
#define QW1  13056           // +32*264
#define QTB  21504           // rope tables cos[1024]|sin[1024]
#define QJ_FLOATS 23552
#define QJ_BYTES (QJ_FLOATS * 4)

#define OA0  0
#define OA1  2304            // 64*36
#define OW0  4608
#define OW1  13056
#define OJ_FLOATS 21504
#define OJ_BYTES (OJ_FLOATS * 4)

__global__ void __launch_bounds__(256, 2) qproj_kernel(const float* __restrict__ fv,
                                                       const float* __restrict__ qw,
                                                       const float* __restrict__ qb)
{
    extern __shared__ float sm[];
    const unsigned smu = (unsigned)__cvta_generic_to_shared(sm);
    float* TB = sm + QTB;

    const int tid  = threadIdx.x;
    const int w    = tid >> 5;
    const int lane = tid & 31;
    const int g    = lane >> 2;
    const int tg   = lane & 3;
    const int b    = blockIdx.x >> 9;
    const int n0   = (blockIdx.x & 511) << 6;
    const int mg   = w >> 2;
    const int cg   = w & 3;
    const int m0   = mg * 32;

    // ---- build rope tables (4 sincos per thread) ----
    #pragma unroll
    for (int e = 0; e < 4; e++) {
        const int idx = tid + e * 256;
        const int pos = idx >> 5;
        const int jj  = idx & 31;
        float ex;
        if (jj < 10)      { const int z = jj;      ex = ((z < 5) ? z : z - 5) / 5.0f; }
        else if (jj < 20) { const int y = jj - 10; ex = ((y < 5) ? y : y - 5) / 5.0f; }
        else              { const int x = jj - 20; ex = ((x < 6) ? x : x - 6) / 6.0f; }
        const float invf = expf(-ex * 9.210340371976184f);
        float sf, cf;
        __sincosf((float)pos * invf, &sf, &cf);
        TB[idx]        = cf;
        TB[1024 + idx] = sf;
    }

    const float* __restrict__ fvb = fv + (size_t)b * Cch * Nn;

    float acc[2][8][4];
    #pragma unroll
    for (int mt = 0; mt < 2; mt++)
        #pragma unroll
        for (int nt = 0; nt < 8; nt++)
            #pragma unroll
            for (int i = 0; i < 4; i++) acc[mt][nt][i] = 0.0f;

    // prefetch iteration 0 into buffer 0
    {
        #pragma unroll
        for (int r = 0; r < 2; r++) {
            const int idx = tid + r * 256;
            const int kk = idx >> 4, cc = idx & 15;
            cpasync16(smu + (QA0 + kk * 72 + cc * 4) * 4,
                      fvb + (size_t)kk * Nn + n0 + cc * 4);
        }
        #pragma unroll
        for (int r = 0; r < 8; r++) {
            const int idx = tid + r * 256;
            const int kk = idx >> 6, cc = idx & 63;
            cpasync16(smu + (QW0 + kk * 264 + cc * 4) * 4,
                      qw + (size_t)kk * Cch + cc * 4);
        }
        CP_COMMIT();
    }

    for (int it = 0; it < 8; it++) {
        const int abuf = (it & 1) ? QA1 : QA0;
        const int wbuf = (it & 1) ? QW1 : QW0;
        if (it < 7) {
            const int k1 = (it + 1) * 32;
            const int a2 = (it & 1) ? QA0 : QA1;
            const int w2 = (it & 1) ? QW0 : QW1;
            #pragma unroll
            for (int r = 0; r < 2; r++) {
                const int idx = tid + r * 256;
                const int kk = idx >> 4, cc = idx & 15;
                cpasync16(smu + (a2 + kk * 72 + cc * 4) * 4,
                          fvb + (size_t)(k1 + kk) * Nn + n0 + cc * 4);
            }
            #pragma unroll
            for (int r = 0; r < 8; r++) {
                const int idx = tid + r * 256;
                const int kk = idx >> 6, cc = idx & 63;
                cpasync16(smu + (w2 + kk * 264 + cc * 4) * 4,
                          qw + (size_t)(k1 + kk) * Cch + cc * 4);
            }
            CP_COMMIT();
            CP_WAIT(1);
        } else {
            CP_WAIT(0);
        }
        __syncthreads();

        const float* As = sm + abuf;
        const float* Ws = sm + wbuf;

        unsigned a[2][4][4];
        #pragma unroll
        for (int mt = 0; mt < 2; mt++) {
            const int row = m0 + mt * 16 + g;
            #pragma unroll
            for (int ks = 0; ks < 4; ks++) {
                const int base = ks * 8 + tg;
                a[mt][ks][0] = f2tf(As[base * 72 + row]);
                a[mt][ks][1] = f2tf(As[base * 72 + row + 8]);
                a[mt][ks][2] = f2tf(As[(base + 4) * 72 + row]);
                a[mt][ks][3] = f2tf(As[(base + 4) * 72 + row + 8]);
            }
        }
        #pragma unroll
        for (int nt = 0; nt < 8; nt++) {
            const int c0 = cg * 64 + nt * 8 + g;
            #pragma unroll
            for (int ks = 0; ks < 4; ks++) {
                const unsigned b0 = f2tf(Ws[(ks * 8 + tg) * 264 + c0]);
                const unsigned b1 = f2tf(Ws[(ks * 8 + tg + 4) * 264 + c0]);
                mma8(acc[0][nt], a[0][ks], b0, b1);
                mma8(acc[1][nt], a[1][ks], b0, b1);
            }
        }
        __syncthreads();
    }

    // write accums into OUT[64][258] (overlays staging buffers)
    #pragma unroll
    for (int mt = 0; mt < 2; mt++) {
        const int row = m0 + mt * 16 + g;
        #pragma unroll
        for (int nt = 0; nt < 8; nt++) {
            const int col = cg * 64 + nt * 8 + 2 * tg;
            *(float2*)&sm[row * 258 + col]       = make_float2(acc[mt][nt][0], acc[mt][nt][1]);
            *(float2*)&sm[(row + 8) * 258 + col] = make_float2(acc[mt][nt][2], acc[mt][nt][3]);
        }
    }
    __syncthreads();

    // epilogue: bias + 3D rope via table; thread = channel c for 64 tokens
    const int c    = tid;
    const int j    = c & 31;
    const int head = c >> 5;
    const int sel  = (j < 10) ? 0 : (j < 20) ? 1 : 2;
    const int part  = (j < 16) ? c + 16 : c - 16;
    const float sgn = (j < 16) ? -1.0f : 1.0f;
    const float qbc = qb[c], qbp = qb[part];

    float* __restrict__ qo = g_qrot + (((size_t)(b * NH + head)) * Nn) * HD + j;
    for (int nn = 0; nn < 64; nn++) {
        const int n  = n0 + nn;
        const int dz = n >> 10;
        const int hy = (n >> 5) & 31;
        const int wx = n & 31;
        const int posv = (sel == 0) ? dz : (sel == 1) ? hy : wx;
        const float cf = TB[posv * 32 + j];
        const float sf = TB[1024 + posv * 32 + j];
        const float qv = sm[nn * 258 + c]    + qbc;
        const float pv = sm[nn * 258 + part] + qbp;
        qo[(size_t)n * HD] = qv * cf + sgn * pv * sf;
    }
}

// ---------------------------------------------------------------------------
// Kernel 3: persistent flash attention, TF32 mma.
// Grid (ASLICE, NH, Bv): each CTA stages K/V for its (b,h) ONCE, then loops
// over query tiles (128 queries each, stride ASLICE). Q fragments are loaded
// directly from gmem (no smem staging, no CTA-wide syncs in the tile loop).
// smem: Ps[128][68] | Kf[256][36] | Vs[256][40] = 110KB -> 2 CTAs/SM.
// ---------------------------------------------------------------------------
#define APS  0                       // Ps: 128*68 = 8704 fl
#define AK   8704
#define AV   (AK + 256*36)           // 17920
#define AT_FLOATS (AV + 256*40)      // 28160
#define AT_BYTES (AT_FLOATS * 4)     // 112640

__global__ void __launch_bounds__(256, 2) attn_kernel()
{
    extern __shared__ float sm[];
    float* Ps = sm + APS;    // [128][68]
    float* Kf = sm + AK;     // [256][36]
    float* Vs = sm + AV;     // [256][40]

    const int tid  = threadIdx.x;
    const int w    = tid >> 5;       // 0..7
    const int lane = tid & 31;
    const int g    = lane >> 2;
    const int tg   = lane & 3;
    const int h    = blockIdx.y;
    const int b    = blockIdx.z;
    const size_t bh = (size_t)(b * NH + h);
    const int qr   = w * 16 + g;     // CTA-local row (Ps index)

    // ---- stage K, V once for this (b,h) ----
    {
        const float4* ksrc = (const float4*)(g_krot + bh * Ss * HD);
        const float4* vsrc = (const float4*)(g_v    + bh * Ss * HD);
        #pragma unroll
        for (int r = 0; r < 8; r++) {
            const int idx = tid + r * 256;        // 0..2047
            const int key = idx >> 3;
            const int c4  = (idx & 7) * 4;
            const float4 fk = ksrc[idx];
            float4 tk;
            tk.x = tfval(fk.x); tk.y = tfval(fk.y); tk.z = tfval(fk.z); tk.w = tfval(fk.w);
            *(float4*)&Kf[key * 36 + c4] = tk;
            const float4 fv4 = vsrc[idx];
            float4 tv;
            tv.x = tfval(fv4.x); tv.y = tfval(fv4.y); tv.z = tfval(fv4.z); tv.w = tfval(fv4.w);
            *(float4*)&Vs[key * 40 + c4] = tv;
        }
    }
    __syncthreads();

    const float* __restrict__ qbase = g_qrot + bh * Nn * HD;

    for (int tile = blockIdx.x; tile < Nn / 128; tile += ASLICE) {
        const int n0   = tile * 128;
        const int row0 = n0 + qr;

        // ---- Q fragments straight from gmem (scale + tf32 inline) ----
        unsigned aq[4][4];
        #pragma unroll
        for (int ks = 0; ks < 4; ks++) {
            const int base = ks * 8 + tg;
            aq[ks][0] = f2tf(qbase[(size_t)row0 * HD + base]       * SCALE);
            aq[ks][1] = f2tf(qbase[(size_t)(row0 + 8) * HD + base] * SCALE);
            aq[ks][2] = f2tf(qbase[(size_t)row0 * HD + base + 4]       * SCALE);
            aq[ks][3] = f2tf(qbase[(size_t)(row0 + 8) * HD + base + 4] * SCALE);
        }

        float m0 = -1e30f, m1 = -1e30f, l0 = 0.0f, l1 = 0.0f;
        float o[4][4];
        #pragma unroll
        for (int nt = 0; nt < 4; nt++)
            #pragma unroll
            for (int i = 0; i < 4; i++) o[nt][i] = 0.0f;

        #pragma unroll
        for (int ch = 0; ch < 4; ch++) {
            // ---- QK^T for 64-key chunk ----
            float c[8][4];
            #pragma unroll
            for (int nt = 0; nt < 8; nt++)
                #pragma unroll
                for (int i = 0; i < 4; i++) c[nt][i] = 0.0f;

            #pragma unroll
            for (int nt = 0; nt < 8; nt++) {
                const int k0 = ch * 64 + nt * 8 + g;
                #pragma unroll
                for (int ks = 0; ks < 4; ks++) {
                    const unsigned b0 = __float_as_uint(Kf[k0 * 36 + ks * 8 + tg]);
                    const unsigned b1 = __float_as_uint(Kf[k0 * 36 + ks * 8 + tg + 4]);
                    mma8(c[nt], aq[ks], b0, b1);
                }
            }

            // ---- chunk row max ----
            float cm0 = -1e30f, cm1 = -1e30f;
            #pragma unroll
            for (int nt = 0; nt < 8; nt++) {
                cm0 = fmaxf(cm0, fmaxf(c[nt][0], c[nt][1]));
                cm1 = fmaxf(cm1, fmaxf(c[nt][2], c[nt][3]));
            }
            cm0 = fmaxf(cm0, __shfl_xor_sync(0xffffffffu, cm0, 1));
            cm0 = fmaxf(cm0, __shfl_xor_sync(0xffffffffu, cm0, 2));
            cm1 = fmaxf(cm1, __shfl_xor_sync(0xffffffffu, cm1, 1));
            cm1 = fmaxf(cm1, __shfl_xor_sync(0xffffffffu, cm1, 2));

            float sc0 = 1.0f, sc1 = 1.0f;
            if (ch == 0) {
                m0 = cm0; m1 = cm1;
            } else {
                const float mn0 = fmaxf(m0, cm0);
                const float mn1 = fmaxf(m1, cm1);
                sc0 = __expf(m0 - mn0);
                sc1 = __expf(m1 - mn1);
                m0 = mn0; m1 = mn1;
            }

            // ---- exp + row sums; convert to tf32 probs ----
            float s0 = 0.0f, s1 = 0.0f;
            #pragma unroll
            for (int nt = 0; nt < 8; nt++) {
                const float p0 = __expf(c[nt][0] - m0);
                const float p1 = __expf(c[nt][1] - m0);
                const float p2 = __expf(c[nt][2] - m1);
                const float p3 = __expf(c[nt][3] - m1);
                s0 += p0 + p1;  s1 += p2 + p3;
                c[nt][0] = tfval(p0); c[nt][1] = tfval(p1);
                c[nt][2] = tfval(p2); c[nt][3] = tfval(p3);
            }
            s0 += __shfl_xor_sync(0xffffffffu, s0, 1);
            s0 += __shfl_xor_sync(0xffffffffu, s0, 2);
            s1 += __shfl_xor_sync(0xffffffffu, s1, 1);
            s1 += __shfl_xor_sync(0xffffffffu, s1, 2);
            if (ch == 0) {
                l0 = s0;  l1 = s1;
            } else {
                l0 = l0 * sc0 + s0;
                l1 = l1 * sc1 + s1;
                #pragma unroll
                for (int nt = 0; nt < 4; nt++) {
                    o[nt][0] *= sc0;  o[nt][1] *= sc0;
                    o[nt][2] *= sc1;  o[nt][3] *= sc1;
                }
            }

            // ---- write chunk probs to per-warp Ps rows ----
            #pragma unroll
            for (int nt = 0; nt < 8; nt++) {
                *(float2*)&Ps[qr * 68 + nt * 8 + 2 * tg]       = make_float2(c[nt][0], c[nt][1]);
                *(float2*)&Ps[(qr + 8) * 68 + nt * 8 + 2 * tg] = make_float2(c[nt][2], c[nt][3]);
            }
            __syncwarp();

            // ---- P @ V for this chunk ----
            #pragma unroll
            for (int s = 0; s < 8; s++) {
                unsigned a[4];
                a[0] = __float_as_uint(Ps[qr * 68 + s * 8 + tg]);
                a[1] = __float_as_uint(Ps[(qr + 8) * 68 + s * 8 + tg]);
                a[2] = __float_as_uint(Ps[qr * 68 + s * 8 + tg + 4]);
                a[3] = __float_as_uint(Ps[(qr + 8) * 68 + s * 8 + tg + 4]);
                const int kk = ch * 64 + s * 8;
                #pragma unroll
                for (int nt = 0; nt < 4; nt++) {
                    const unsigned b0 = __float_as_uint(Vs[(kk + tg) * 40 + nt * 8 + g]);
                    const unsigned b1 = __float_as_uint(Vs[(kk + tg + 4) * 40 + nt * 8 + g]);
                    mma8(o[nt], a, b0, b1);
                }
            }
            __syncwarp();
        }

        // ---- epilogue: normalize + store ----
        const float r0 = 1.0f / l0;
        const float r1 = 1.0f / l1;
        #pragma unroll
        for (int nt = 0; nt < 4; nt++) {
            const int hd = nt * 8 + 2 * tg;
            float* p0 = g_att + ((size_t)(b * Nn + row0)) * Cch + h * HD + hd;
            float* p1 = g_att + ((size_t)(b * Nn + row0 + 8)) * Cch + h * HD + hd;
            *(float2*)p0 = make_float2(o[nt][0] * r0, o[nt][1] * r0);
            *(float2*)p1 = make_float2(o[nt][2] * r1, o[nt][3] * r1);
        }
    }
}

// ---------------------------------------------------------------------------
// Kernel 4: O projection + transpose, TF32 mma, cp.async double-buffered.
// ---------------------------------------------------------------------------
__global__ void __launch_bounds__(256, 2) oproj_kernel(const float* __restrict__ ow,
                                                       const float* __restrict__ ob,
                                                       float* __restrict__ out)
{
    extern __shared__ float sm[];
    const unsigned smu = (unsigned)__cvta_generic_to_shared(sm);

    const int tid  = threadIdx.x;
    const int w    = tid >> 5;
    const int lane = tid & 31;
    const int g    = lane >> 2;
    const int tg   = lane & 3;
    const int b    = blockIdx.x >> 9;
    const int n0   = (blockIdx.x & 511) << 6;
    const int mg   = w >> 2;
    const int cg   = w & 3;
    const int m0   = mg * 32;

    const float* __restrict__ att = g_att + ((size_t)(b * Nn + n0)) * Cch;

    float acc[2][8][4];
    #pragma unroll
    for (int mt = 0; mt < 2; mt++)
        #pragma unroll
        for (int nt = 0; nt < 8; nt++)
            #pragma unroll
            for (int i = 0; i < 4; i++) acc[mt][nt][i] = 0.0f;

    // prefetch iter 0 into buffer 0
    {
        #pragma unroll
        for (int r = 0; r < 2; r++) {
            const int idx = tid + r * 256;       // 0..511
            const int nn = idx >> 3, cc = idx & 7;
            cpasync16(smu + (OA0 + nn * 36 + cc * 4) * 4,
                      att + (size_t)nn * Cch + cc * 4);
        }
        #pragma unroll
        for (int r = 0; r < 8; r++) {
            const int idx = tid + r * 256;
            const int kk = idx >> 6, cc = idx & 63;
            cpasync16(smu + (OW0 + kk * 264 + cc * 4) * 4,
                      ow + (size_t)kk * Cch + cc * 4);
        }
        CP_COMMIT();
    }

    for (int it = 0; it < 8; it++) {
        const int abuf = (it & 1) ? OA1 : OA0;
        const int wbuf = (it & 1) ? OW1 : OW0;
        if (it < 7) {
            const int k1 = (it + 1) * 32;
            const int a2 = (it & 1) ? OA0 : OA1;
            const int w2 = (it & 1) ? OW0 : OW1;
            #pragma unroll
            for (int r = 0; r < 2; r++) {
                const int idx = tid + r * 256;
                const int nn = idx >> 3, cc = idx & 7;
                cpasync16(smu + (a2 + nn * 36 + cc * 4) * 4,
                          att + (size_t)nn * Cch + k1 + cc * 4);
            }
            #pragma unroll
            for (int r = 0; r < 8; r++) {
                const int idx = tid + r * 256;
                const int kk = idx >> 6, cc = idx & 63;
                cpasync16(smu + (w2 + kk * 264 + cc * 4) * 4,
                          ow + (size_t)(k1 + kk) * Cch + cc * 4);
            }
            CP_COMMIT();
            CP_WAIT(1);
        } else {
            CP_WAIT(0);
        }
        __syncthreads();

        const float* As = sm + abuf;
        const float* Ws = sm + wbuf;

        unsigned a[2][4][4];
        #pragma unroll
        for (int mt = 0; mt < 2; mt++) {
            const int row = m0 + mt * 16 + g;
            #pragma unroll
            for (int ks = 0; ks < 4; ks++) {
                const int base = ks * 8 + tg;
                a[mt][ks][0] = f2tf(As[row * 36 + base]);
                a[mt][ks][1] = f2tf(As[(row + 8) * 36 + base]);
                a[mt][ks][2] = f2tf(As[row * 36 + base + 4]);
                a[mt][ks][3] = f2tf(As[(row + 8) * 36 + base + 4]);
            }
        }
        #pragma unroll
        for (int nt = 0; nt < 8; nt++) {
            const int c0 = cg * 64 + nt * 8 + g;
            #pragma unroll
            for (int ks = 0; ks < 4; ks++) {
                const unsigned b0 = f2tf(Ws[(ks * 8 + tg) * 264 + c0]);
                const unsigned b1 = f2tf(Ws[(ks * 8 + tg + 4) * 264 + c0]);
                mma8(acc[0][nt], a[0][ks], b0, b1);
                mma8(acc[1][nt], a[1][ks], b0, b1);
            }
        }
        __syncthreads();
    }

    #pragma unroll
    for (int mt = 0; mt < 2; mt++) {
        const int row = m0 + mt * 16 + g;
        #pragma unroll
        for (int nt = 0; nt < 8; nt++) {
            const int col = cg * 64 + nt * 8 + 2 * tg;
            *(float2*)&sm[row * 258 + col]       = make_float2(acc[mt][nt][0], acc[mt][nt][1]);
            *(float2*)&sm[(row + 8) * 258 + col] = make_float2(acc[mt][nt][2], acc[mt][nt][3]);
        }
    }
    __syncthreads();

    // transposed coalesced store: out[b][c][n0 + token]
    const int grp = tid >> 5;
    float* __restrict__ obp = out + (size_t)b * Cch * Nn + n0 + lane;
    #pragma unroll 4
    for (int it = 0; it < 32; it++) {
        const int c = it * 8 + grp;
        const float bias = ob[c];
        obp[(size_t)c * Nn]      = sm[lane * 258 + c] + bias;
        obp[(size_t)c * Nn + 32] = sm[(lane + 32) * 258 + c] + bias;
    }
}

// ---------------------------------------------------------------------------
extern "C" void kernel_launch(void* const* d_in, const int* in_sizes, int n_in,
                              void* d_out, int out_size)
{
    const float* fused_visual = (const float*)d_in[0];
    const float* text_emb     = (const float*)d_in[1];
    const float* q_w = (const float*)d_in[2];
    const float* q_b = (const float*)d_in[3];
    const float* k_w = (const float*)d_in[4];
    const float* k_b = (const float*)d_in[5];
    const float* v_w = (const float*)d_in[6];
    const float* v_b = (const float*)d_in[7];
    const float* o_w = (const float*)d_in[8];
    const float* o_b = (const float*)d_in[9];
    const float* m1_w = (const float*)d_in[10];
    const float* m1_b = (const float*)d_in[11];
    const float* m2_w = (const float*)d_in[12];
    const float* m2_b = (const float*)d_in[13];
    float* out = (float*)d_out;

    static int smem_ok = -1;
    if (smem_ok < 0) {
        cudaFuncSetAttribute(attn_kernel,  cudaFuncAttributeMaxDynamicSharedMemorySize, AT_BYTES);
        cudaFuncSetAttribute(qproj_kernel, cudaFuncAttributeMaxDynamicSharedMemorySize, QJ_BYTES);
        cudaFuncSetAttribute(oproj_kernel, cudaFuncAttributeMaxDynamicSharedMemorySize, OJ_BYTES);
        smem_ok = 1;
    }

    text_kernel<<<(Bv * Ss) / 8, 256>>>(text_emb, k_w, k_b, v_w, v_b, m1_w, m1_b, m2_w, m2_b);
    qproj_kernel<<<Bv * (Nn / 64), 256, QJ_BYTES>>>(fused_visual, q_w, q_b);
    attn_kernel<<<dim3(ASLICE, NH, Bv), 256, AT_BYTES>>>();
    oproj_kernel<<<Bv * (Nn / 64), 256, OJ_BYTES>>>(o_w, o_b, out);
}

// round 12
// speedup vs baseline: 1.0082x; 1.0082x over previous
#include <cuda_runtime.h>
#include <math.h>

// ---------------- problem constants ----------------
#define Bv   2
#define Cch  256
#define Nn   32768           // D*H*W
#define Ss   256
#define TDd  512
#define NH   8
#define HD   32
#define SCALE 0.17677669529663687f    // 32^-0.5
#define QSCALE 0.2550396392825023f    // SCALE * log2(e)

// ---------------- scratch ----------------
__device__ float g_krot[Bv * NH * Ss * HD];          // [b,h,s,hd]
__device__ float g_v   [Bv * NH * Ss * HD];          // [b,h,s,hd]
__device__ float g_qrot[(size_t)Bv * NH * Nn * HD];  // [b,h,n,hd]  64MB
__device__ float g_att [(size_t)Bv * Nn * Cch];      // [b,n,c]     64MB

// ---------------- helpers ----------------
__device__ __forceinline__ unsigned f2tf(float x) {
    unsigned u;
    asm("cvt.rna.tf32.f32 %0, %1;" : "=r"(u) : "f"(x));
    return u;
}
__device__ __forceinline__ float tfval(float x) { return __uint_as_float(f2tf(x)); }

__device__ __forceinline__ void mma8(float c[4], const unsigned a[4],
                                     unsigned b0, unsigned b1) {
    asm volatile(
        "mma.sync.aligned.m16n8k8.row.col.f32.tf32.tf32.f32 "
        "{%0,%1,%2,%3},{%4,%5,%6,%7},{%8,%9},{%0,%1,%2,%3};"
        : "+f"(c[0]), "+f"(c[1]), "+f"(c[2]), "+f"(c[3])
        : "r"(a[0]), "r"(a[1]), "r"(a[2]), "r"(a[3]), "r"(b0), "r"(b1));
}

__device__ __forceinline__ void cpasync16(unsigned dst, const void* src) {
    asm volatile("cp.async.ca.shared.global [%0], [%1], 16;" :: "r"(dst), "l"(src));
}
#define CP_COMMIT()  asm volatile("cp.async.commit_group;")
#define CP_WAIT(n)   asm volatile("cp.async.wait_group %0;" :: "n"(n))

// ---------------------------------------------------------------------------
// Kernel 1: text side (K/V proj, MLP phase, rope on K). 64 CTAs, tiny. FFMA.
// ---------------------------------------------------------------------------
__global__ void text_kernel(const float* __restrict__ text,
                            const float* __restrict__ k_w, const float* __restrict__ k_b,
                            const float* __restrict__ v_w, const float* __restrict__ v_b,
                            const float* __restrict__ m1_w, const float* __restrict__ m1_b,
                            const float* __restrict__ m2_w, const float* __restrict__ m2_b)
{
    __shared__ float t_s[8][TDd];
    __shared__ float h_s[8][Cch];
    __shared__ float k_s[8][Cch];

    const int tid  = threadIdx.x;
    const int row0 = blockIdx.x * 8;

    #pragma unroll
    for (int r = 0; r < 8; r++) {
        t_s[r][tid]       = text[(size_t)(row0 + r) * TDd + tid];
        t_s[r][tid + 256] = text[(size_t)(row0 + r) * TDd + tid + 256];
    }
    __syncthreads();

    float ka[8], va[8], ha[8];
    #pragma unroll
    for (int r = 0; r < 8; r++) { ka[r] = k_b[tid]; va[r] = v_b[tid]; ha[r] = m1_b[tid]; }

    for (int i = 0; i < TDd; i++) {
        const float wk = k_w[i * Cch + tid];
        const float wv = v_w[i * Cch + tid];
        const float wm = m1_w[i * Cch + tid];
        #pragma unroll
        for (int r = 0; r < 8; r++) {
            const float t = t_s[r][i];
            ka[r] += t * wk;  va[r] += t * wv;  ha[r] += t * wm;
        }
    }

    #pragma unroll
    for (int r = 0; r < 8; r++) {
        const float x = ha[r];
        h_s[r][tid] = 0.5f * x * (1.0f + erff(x * 0.7071067811865475f));
        k_s[r][tid] = ka[r];
    }
    __syncthreads();

    float pa[8];
    #pragma unroll
    for (int r = 0; r < 8; r++) pa[r] = m2_b[tid];
    for (int i = 0; i < Cch; i++) {
        const float wm2 = m2_w[i * Cch + tid];
        #pragma unroll
        for (int r = 0; r < 8; r++) pa[r] += h_s[r][i] * wm2;
    }

    const int j    = tid & 31;
    const int head = tid >> 5;
    const int part = (j < 16) ? tid + 16 : tid - 16;
    const float sgn = (j < 16) ? -1.0f : 1.0f;

    #pragma unroll
    for (int r = 0; r < 8; r++) {
        const int row = row0 + r;
        const int b = row >> 8;
        const int s = row & 255;
        float sf, cf;
        sincosf(pa[r], &sf, &cf);
        const float krot = k_s[r][tid] * cf + sgn * k_s[r][part] * sf;
        const int o = ((b * NH + head) * Ss + s) * HD + j;
        g_krot[o] = krot;
        g_v[o]    = va[r];
    }
}

// ---------------------------------------------------------------------------
// Projection kernels: TF32 mma, cp.async double-buffered staging.
// ---------------------------------------------------------------------------
#define QA0  0
#define QA1  2304            // 32*72
#define QW0  4608
#define QW1  13056           // +32*264
#define QTB  21504           // rope tables cos[1024]|sin[1024]
#define QJ_FLOATS 23552
#define QJ_BYTES (QJ_FLOATS * 4)

#define OA0  0
#define OA1  2304            // 64*36
#define OW0  4608
#define OW1  13056
#define OJ_FLOATS 21504
#define OJ_BYTES (OJ_FLOATS * 4)

__global__ void __launch_bounds__(256, 2) qproj_kernel(const float* __restrict__ fv,
                                                       const float* __restrict__ qw,
                                                       const float* __restrict__ qb)
{
    extern __shared__ float sm[];
    const unsigned smu = (unsigned)__cvta_generic_to_shared(sm);
    float* TB = sm + QTB;

    const int tid  = threadIdx.x;
    const int w    = tid >> 5;
    const int lane = tid & 31;
    const int g    = lane >> 2;
    const int tg   = lane & 3;
    const int b    = blockIdx.x >> 9;
    const int n0   = (blockIdx.x & 511) << 6;
    const int mg   = w >> 2;
    const int cg   = w & 3;
    const int m0   = mg * 32;

    // ---- build rope tables (4 sincos per thread) ----
    #pragma unroll
    for (int e = 0; e < 4; e++) {
        const int idx = tid + e * 256;
        const int pos = idx >> 5;
        const int jj  = idx & 31;
        float ex;
        if (jj < 10)      { const int z = jj;      ex = ((z < 5) ? z : z - 5) / 5.0f; }
        else if (jj < 20) { const int y = jj - 10; ex = ((y < 5) ? y : y - 5) / 5.0f; }
        else              { const int x = jj - 20; ex = ((x < 6) ? x : x - 6) / 6.0f; }
        const float invf = expf(-ex * 9.210340371976184f);
        float sf, cf;
        __sincosf((float)pos * invf, &sf, &cf);
        TB[idx]        = cf;
        TB[1024 + idx] = sf;
    }

    const float* __restrict__ fvb = fv + (size_t)b * Cch * Nn;

    float acc[2][8][4];
    #pragma unroll
    for (int mt = 0; mt < 2; mt++)
        #pragma unroll
        for (int nt = 0; nt < 8; nt++)
            #pragma unroll
            for (int i = 0; i < 4; i++) acc[mt][nt][i] = 0.0f;

    // prefetch iteration 0 into buffer 0
    {
        #pragma unroll
        for (int r = 0; r < 2; r++) {
            const int idx = tid + r * 256;
            const int kk = idx >> 4, cc = idx & 15;
            cpasync16(smu + (QA0 + kk * 72 + cc * 4) * 4,
                      fvb + (size_t)kk * Nn + n0 + cc * 4);
        }
        #pragma unroll
        for (int r = 0; r < 8; r++) {
            const int idx = tid + r * 256;
            const int kk = idx >> 6, cc = idx & 63;
            cpasync16(smu + (QW0 + kk * 264 + cc * 4) * 4,
                      qw + (size_t)kk * Cch + cc * 4);
        }
        CP_COMMIT();
    }

    for (int it = 0; it < 8; it++) {
        const int abuf = (it & 1) ? QA1 : QA0;
        const int wbuf = (it & 1) ? QW1 : QW0;
        if (it < 7) {
            const int k1 = (it + 1) * 32;
            const int a2 = (it & 1) ? QA0 : QA1;
            const int w2 = (it & 1) ? QW0 : QW1;
            #pragma unroll
            for (int r = 0; r < 2; r++) {
                const int idx = tid + r * 256;
                const int kk = idx >> 4, cc = idx & 15;
                cpasync16(smu + (a2 + kk * 72 + cc * 4) * 4,
                          fvb + (size_t)(k1 + kk) * Nn + n0 + cc * 4);
            }
            #pragma unroll
            for (int r = 0; r < 8; r++) {
                const int idx = tid + r * 256;
                const int kk = idx >> 6, cc = idx & 63;
                cpasync16(smu + (w2 + kk * 264 + cc * 4) * 4,
                          qw + (size_t)(k1 + kk) * Cch + cc * 4);
            }
            CP_COMMIT();
            CP_WAIT(1);
        } else {
            CP_WAIT(0);
        }
        __syncthreads();

        const float* As = sm + abuf;
        const float* Ws = sm + wbuf;

        unsigned a[2][4][4];
        #pragma unroll
        for (int mt = 0; mt < 2; mt++) {
            const int row = m0 + mt * 16 + g;
            #pragma unroll
            for (int ks = 0; ks < 4; ks++) {
                const int base = ks * 8 + tg;
                a[mt][ks][0] = f2tf(As[base * 72 + row]);
                a[mt][ks][1] = f2tf(As[base * 72 + row + 8]);
                a[mt][ks][2] = f2tf(As[(base + 4) * 72 + row]);
                a[mt][ks][3] = f2tf(As[(base + 4) * 72 + row + 8]);
            }
        }
        #pragma unroll
        for (int nt = 0; nt < 8; nt++) {
            const int c0 = cg * 64 + nt * 8 + g;
            #pragma unroll
            for (int ks = 0; ks < 4; ks++) {
                const unsigned b0 = f2tf(Ws[(ks * 8 + tg) * 264 + c0]);
                const unsigned b1 = f2tf(Ws[(ks * 8 + tg + 4) * 264 + c0]);
                mma8(acc[0][nt], a[0][ks], b0, b1);
                mma8(acc[1][nt], a[1][ks], b0, b1);
            }
        }
        __syncthreads();
    }

    // write accums into OUT[64][258] (overlays staging buffers)
    #pragma unroll
    for (int mt = 0; mt < 2; mt++) {
        const int row = m0 + mt * 16 + g;
        #pragma unroll
        for (int nt = 0; nt < 8; nt++) {
            const int col = cg * 64 + nt * 8 + 2 * tg;
            *(float2*)&sm[row * 258 + col]       = make_float2(acc[mt][nt][0], acc[mt][nt][1]);
            *(float2*)&sm[(row + 8) * 258 + col] = make_float2(acc[mt][nt][2], acc[mt][nt][3]);
        }
    }
    __syncthreads();

    // epilogue: bias + 3D rope via table; thread = channel c for 64 tokens
    const int c    = tid;
    const int j    = c & 31;
    const int head = c >> 5;
    const int sel  = (j < 10) ? 0 : (j < 20) ? 1 : 2;
    const int part  = (j < 16) ? c + 16 : c - 16;
    const float sgn = (j < 16) ? -1.0f : 1.0f;
    const float qbc = qb[c], qbp = qb[part];

    float* __restrict__ qo = g_qrot + (((size_t)(b * NH + head)) * Nn) * HD + j;
    for (int nn = 0; nn < 64; nn++) {
        const int n  = n0 + nn;
        const int dz = n >> 10;
        const int hy = (n >> 5) & 31;
        const int wx = n & 31;
        const int posv = (sel == 0) ? dz : (sel == 1) ? hy : wx;
        const float cf = TB[posv * 32 + j];
        const float sf = TB[1024 + posv * 32 + j];
        const float qv = sm[nn * 258 + c]    + qbc;
        const float pv = sm[nn * 258 + part] + qbp;
        qo[(size_t)n * HD] = qv * cf + sgn * pv * sf;
    }
}

// ---------------------------------------------------------------------------
// Kernel 3: flash attention, TF32 mma. CTA = 128 queries (8 warps).
// NEW: 128-key register groups -> ONE softmax pass per group (one rescale
// per tile instead of three), exp2-folded scaling, no cvt on probs.
// smem: union{Qs[128][36], Ps[128][68]} | Kf[256][36] | Vs[256][40] -> 2 CTA/SM
// ---------------------------------------------------------------------------
#define APQ  0                       // union: Qs (4608 fl) / Ps (8704 fl)
#define AK   8704
#define AV   (AK + 256*36)           // 17920
#define AT_FLOATS (AV + 256*40)      // 28160
#define AT_BYTES (AT_FLOATS * 4)     // 112640

__global__ void __launch_bounds__(256, 2) attn_kernel()
{
    extern __shared__ float sm[];
    float* Qs = sm + APQ;    // [128][36]  (staging only)
    float* Ps = sm + APQ;    // [128][68]  (after aq-load)
    float* Kf = sm + AK;     // [256][36]
    float* Vs = sm + AV;     // [256][40]

    const int tid  = threadIdx.x;
    const int w    = tid >> 5;       // 0..7
    const int lane = tid & 31;
    const int g    = lane >> 2;
    const int tg   = lane & 3;
    const int n0   = blockIdx.x * 128;
    const int h    = blockIdx.y;
    const int b    = blockIdx.z;
    const size_t bh = (size_t)(b * NH + h);
    const int qr   = w * 16 + g;

    // ---- stage Q (QSCALE + tf32), K, V ----
    {
        const float4* qsrc = (const float4*)(g_qrot + (bh * Nn + n0) * HD);
        #pragma unroll
        for (int r = 0; r < 4; r++) {
            const int idx = tid + r * 256;        // 0..1023
            const float4 f = qsrc[idx];
            const int row = idx >> 3;
            const int c4  = (idx & 7) * 4;
            float4 t;
            t.x = tfval(f.x * QSCALE); t.y = tfval(f.y * QSCALE);
            t.z = tfval(f.z * QSCALE); t.w = tfval(f.w * QSCALE);
            *(float4*)&Qs[row * 36 + c4] = t;
        }
        const float4* ksrc = (const float4*)(g_krot + bh * Ss * HD);
        const float4* vsrc = (const float4*)(g_v    + bh * Ss * HD);
        #pragma unroll
        for (int r = 0; r < 8; r++) {
            const int idx = tid + r * 256;        // 0..2047
            const int key = idx >> 3;
            const int c4  = (idx & 7) * 4;
            const float4 fk = ksrc[idx];
            float4 tk;
            tk.x = tfval(fk.x); tk.y = tfval(fk.y); tk.z = tfval(fk.z); tk.w = tfval(fk.w);
            *(float4*)&Kf[key * 36 + c4] = tk;
            const float4 fv4 = vsrc[idx];
            float4 tv;
            tv.x = tfval(fv4.x); tv.y = tfval(fv4.y); tv.z = tfval(fv4.z); tv.w = tfval(fv4.w);
            *(float4*)&Vs[key * 40 + c4] = tv;
        }
    }
    __syncthreads();

    // ---- load Q a-frags (held for whole kernel) ----
    unsigned aq[4][4];
    #pragma unroll
    for (int ks = 0; ks < 4; ks++) {
        const int base = ks * 8 + tg;
        aq[ks][0] = __float_as_uint(Qs[qr * 36 + base]);
        aq[ks][1] = __float_as_uint(Qs[(qr + 8) * 36 + base]);
        aq[ks][2] = __float_as_uint(Qs[qr * 36 + base + 4]);
        aq[ks][3] = __float_as_uint(Qs[(qr + 8) * 36 + base + 4]);
    }
    __syncthreads();   // Qs dead; Ps may now overlay it

    float m0, m1, l0, l1;
    float o[4][4];
    #pragma unroll
    for (int nt = 0; nt < 4; nt++)
        #pragma unroll
        for (int i = 0; i < 4; i++) o[nt][i] = 0.0f;

    #pragma unroll
    for (int grp = 0; grp < 2; grp++) {
        // ---- QK^T for 128-key group (scores in log2 units) ----
        float c[16][4];
        #pragma unroll
        for (int nt = 0; nt < 16; nt++)
            #pragma unroll
            for (int i = 0; i < 4; i++) c[nt][i] = 0.0f;

        #pragma unroll
        for (int nt = 0; nt < 16; nt++) {
            const int k0 = grp * 128 + nt * 8 + g;
            #pragma unroll
            for (int ks = 0; ks < 4; ks++) {
                const unsigned b0 = __float_as_uint(Kf[k0 * 36 + ks * 8 + tg]);
                const unsigned b1 = __float_as_uint(Kf[k0 * 36 + ks * 8 + tg + 4]);
                mma8(c[nt], aq[ks], b0, b1);
            }
        }

        // ---- group row max ----
        float cm0 = -1e30f, cm1 = -1e30f;
        #pragma unroll
        for (int nt = 0; nt < 16; nt++) {
            cm0 = fmaxf(cm0, fmaxf(c[nt][0], c[nt][1]));
            cm1 = fmaxf(cm1, fmaxf(c[nt][2], c[nt][3]));
        }
        cm0 = fmaxf(cm0, __shfl_xor_sync(0xffffffffu, cm0, 1));
        cm0 = fmaxf(cm0, __shfl_xor_sync(0xffffffffu, cm0, 2));
        cm1 = fmaxf(cm1, __shfl_xor_sync(0xffffffffu, cm1, 1));
        cm1 = fmaxf(cm1, __shfl_xor_sync(0xffffffffu, cm1, 2));

        float sc0 = 1.0f, sc1 = 1.0f;
        if (grp == 0) {
            m0 = cm0; m1 = cm1;
        } else {
            const float mn0 = fmaxf(m0, cm0);
            const float mn1 = fmaxf(m1, cm1);
            sc0 = exp2f(m0 - mn0);
            sc1 = exp2f(m1 - mn1);
            m0 = mn0; m1 = mn1;
        }

        // ---- exp2 + row sums (probs kept as raw fp32 -> tf32-by-truncation) ----
        float s0 = 0.0f, s1 = 0.0f;
        #pragma unroll
        for (int nt = 0; nt < 16; nt++) {
            const float p0 = exp2f(c[nt][0] - m0);
            const float p1 = exp2f(c[nt][1] - m0);
            const float p2 = exp2f(c[nt][2] - m1);
            const float p3 = exp2f(c[nt][3] - m1);
            s0 += p0 + p1;  s1 += p2 + p3;
            c[nt][0] = p0; c[nt][1] = p1; c[nt][2] = p2; c[nt][3] = p3;
        }
        s0 += __shfl_xor_sync(0xffffffffu, s0, 1);
        s0 += __shfl_xor_sync(0xffffffffu, s0, 2);
        s1 += __shfl_xor_sync(0xffffffffu, s1, 1);
        s1 += __shfl_xor_sync(0xffffffffu, s1, 2);
        if (grp == 0) {
            l0 = s0;  l1 = s1;
        } else {
            l0 = l0 * sc0 + s0;
            l1 = l1 * sc1 + s1;
            #pragma unroll
            for (int nt = 0; nt < 4; nt++) {
                o[nt][0] *= sc0;  o[nt][1] *= sc0;
                o[nt][2] *= sc1;  o[nt][3] *= sc1;
            }
        }

        // ---- two 64-key chunks: Ps round-trip + P@V ----
        #pragma unroll
        for (int hf = 0; hf < 2; hf++) {
            #pragma unroll
            for (int nt2 = 0; nt2 < 8; nt2++) {
                const int nt = hf * 8 + nt2;
                *(float2*)&Ps[qr * 68 + nt2 * 8 + 2 * tg]       = make_float2(c[nt][0], c[nt][1]);
                *(float2*)&Ps[(qr + 8) * 68 + nt2 * 8 + 2 * tg] = make_float2(c[nt][2], c[nt][3]);
            }
            __syncwarp();

            #pragma unroll
            for (int s = 0; s < 8; s++) {
                unsigned a[4];
                a[0] = __float_as_uint(Ps[qr * 68 + s * 8 + tg]);
                a[1] = __float_as_uint(Ps[(qr + 8) * 68 + s * 8 + tg]);
                a[2] = __float_as_uint(Ps[qr * 68 + s * 8 + tg + 4]);
                a[3] = __float_as_uint(Ps[(qr + 8) * 68 + s * 8 + tg + 4]);
                const int kk = grp * 128 + hf * 64 + s * 8;
                #pragma unroll
                for (int nt3 = 0; nt3 < 4; nt3++) {
                    const unsigned b0 = __float_as_uint(Vs[(kk + tg) * 40 + nt3 * 8 + g]);
                    const unsigned b1 = __float_as_uint(Vs[(kk + tg + 4) * 40 + nt3 * 8 + g]);
                    mma8(o[nt3], a, b0, b1);
                }
            }
            __syncwarp();
        }
    }

    // ---- epilogue: normalize + store ----
    const float r0 = 1.0f / l0;
    const float r1 = 1.0f / l1;
    #pragma unroll
    for (int nt = 0; nt < 4; nt++) {
        const int hd = nt * 8 + 2 * tg;
        float* p0 = g_att + ((size_t)(b * Nn + n0 + qr)) * Cch + h * HD + hd;
        float* p1 = g_att + ((size_t)(b * Nn + n0 + qr + 8)) * Cch + h * HD + hd;
        *(float2*)p0 = make_float2(o[nt][0] * r0, o[nt][1] * r0);
        *(float2*)p1 = make_float2(o[nt][2] * r1, o[nt][3] * r1);
    }
}

// ---------------------------------------------------------------------------
// Kernel 4: O projection + transpose, TF32 mma, cp.async double-buffered.
// ---------------------------------------------------------------------------
__global__ void __launch_bounds__(256, 2) oproj_kernel(const float* __restrict__ ow,
                                                       const float* __restrict__ ob,
                                                       float* __restrict__ out)
{
    extern __shared__ float sm[];
    const unsigned smu = (unsigned)__cvta_generic_to_shared(sm);

    const int tid  = threadIdx.x;
    const int w    = tid >> 5;
    const int lane = tid & 31;
    const int g    = lane >> 2;
    const int tg   = lane & 3;
    const int b    = blockIdx.x >> 9;
    const int n0   = (blockIdx.x & 511) << 6;
    const int mg   = w >> 2;
    const int cg   = w & 3;
    const int m0   = mg * 32;

    const float* __restrict__ att = g_att + ((size_t)(b * Nn + n0)) * Cch;

    float acc[2][8][4];
    #pragma unroll
    for (int mt = 0; mt < 2; mt++)
        #pragma unroll
        for (int nt = 0; nt < 8; nt++)
            #pragma unroll
            for (int i = 0; i < 4; i++) acc[mt][nt][i] = 0.0f;

    // prefetch iter 0 into buffer 0
    {
        #pragma unroll
        for (int r = 0; r < 2; r++) {
            const int idx = tid + r * 256;       // 0..511
            const int nn = idx >> 3, cc = idx & 7;
            cpasync16(smu + (OA0 + nn * 36 + cc * 4) * 4,
                      att + (size_t)nn * Cch + cc * 4);
        }
        #pragma unroll
        for (int r = 0; r < 8; r++) {
            const int idx = tid + r * 256;
            const int kk = idx >> 6, cc = idx & 63;
            cpasync16(smu + (OW0 + kk * 264 + cc * 4) * 4,
                      ow + (size_t)kk * Cch + cc * 4);
        }
        CP_COMMIT();
    }

    for (int it = 0; it < 8; it++) {
        const int abuf = (it & 1) ? OA1 : OA0;
        const int wbuf = (it & 1) ? OW1 : OW0;
        if (it < 7) {
            const int k1 = (it + 1) * 32;
            const int a2 = (it & 1) ? OA0 : OA1;
            const int w2 = (it & 1) ? OW0 : OW1;
            #pragma unroll
            for (int r = 0; r < 2; r++) {
                const int idx = tid + r * 256;
                const int nn = idx >> 3, cc = idx & 7;
                cpasync16(smu + (a2 + nn * 36 + cc * 4) * 4,
                          att + (size_t)nn * Cch + k1 + cc * 4);
            }
            #pragma unroll
            for (int r = 0; r < 8; r++) {
                const int idx = tid + r * 256;
                const int kk = idx >> 6, cc = idx & 63;
                cpasync16(smu + (w2 + kk * 264 + cc * 4) * 4,
                          ow + (size_t)(k1 + kk) * Cch + cc * 4);
            }
            CP_COMMIT();
            CP_WAIT(1);
        } else {
            CP_WAIT(0);
        }
        __syncthreads();

        const float* As = sm + abuf;
        const float* Ws = sm + wbuf;

        unsigned a[2][4][4];
        #pragma unroll
        for (int mt = 0; mt < 2; mt++) {
            const int row = m0 + mt * 16 + g;
            #pragma unroll
            for (int ks = 0; ks < 4; ks++) {
                const int base = ks * 8 + tg;
                a[mt][ks][0] = f2tf(As[row * 36 + base]);
                a[mt][ks][1] = f2tf(As[(row + 8) * 36 + base]);
                a[mt][ks][2] = f2tf(As[row * 36 + base + 4]);
                a[mt][ks][3] = f2tf(As[(row + 8) * 36 + base + 4]);
            }
        }
        #pragma unroll
        for (int nt = 0; nt < 8; nt++) {
            const int c0 = cg * 64 + nt * 8 + g;
            #pragma unroll
            for (int ks = 0; ks < 4; ks++) {
                const unsigned b0 = f2tf(Ws[(ks * 8 + tg) * 264 + c0]);
                const unsigned b1 = f2tf(Ws[(ks * 8 + tg + 4) * 264 + c0]);
                mma8(acc[0][nt], a[0][ks], b0, b1);
                mma8(acc[1][nt], a[1][ks], b0, b1);
            }
        }
        __syncthreads();
    }

    #pragma unroll
    for (int mt = 0; mt < 2; mt++) {
        const int row = m0 + mt * 16 + g;
        #pragma unroll
        for (int nt = 0; nt < 8; nt++) {
            const int col = cg * 64 + nt * 8 + 2 * tg;
            *(float2*)&sm[row * 258 + col]       = make_float2(acc[mt][nt][0], acc[mt][nt][1]);
            *(float2*)&sm[(row + 8) * 258 + col] = make_float2(acc[mt][nt][2], acc[mt][nt][3]);
        }
    }
    __syncthreads();

    // transposed coalesced store: out[b][c][n0 + token]
    const int grp = tid >> 5;
    float* __restrict__ obp = out + (size_t)b * Cch * Nn + n0 + lane;
    #pragma unroll 4
    for (int it = 0; it < 32; it++) {
        const int c = it * 8 + grp;
        const float bias = ob[c];
        obp[(size_t)c * Nn]      = sm[lane * 258 + c] + bias;
        obp[(size_t)c * Nn + 32] = sm[(lane + 32) * 258 + c] + bias;
    }
}

// ---------------------------------------------------------------------------
extern "C" void kernel_launch(void* const* d_in, const int* in_sizes, int n_in,
                              void* d_out, int out_size)
{
    const float* fused_visual = (const float*)d_in[0];
    const float* text_emb     = (const float*)d_in[1];
    const float* q_w = (const float*)d_in[2];
    const float* q_b = (const float*)d_in[3];
    const float* k_w = (const float*)d_in[4];
    const float* k_b = (const float*)d_in[5];
    const float* v_w = (const float*)d_in[6];
    const float* v_b = (const float*)d_in[7];
    const float* o_w = (const float*)d_in[8];
    const float* o_b = (const float*)d_in[9];
    const float* m1_w = (const float*)d_in[10];
    const float* m1_b = (const float*)d_in[11];
    const float* m2_w = (const float*)d_in[12];
    const float* m2_b = (const float*)d_in[13];
    float* out = (float*)d_out;

    static int smem_ok = -1;
    if (smem_ok < 0) {
        cudaFuncSetAttribute(attn_kernel,  cudaFuncAttributeMaxDynamicSharedMemorySize, AT_BYTES);
        cudaFuncSetAttribute(qproj_kernel, cudaFuncAttributeMaxDynamicSharedMemorySize, QJ_BYTES);
        cudaFuncSetAttribute(oproj_kernel, cudaFuncAttributeMaxDynamicSharedMemorySize, OJ_BYTES);
        smem_ok = 1;
    }

    text_kernel<<<(Bv * Ss) / 8, 256>>>(text_emb, k_w, k_b, v_w, v_b, m1_w, m1_b, m2_w, m2_b);
    qproj_kernel<<<Bv * (Nn / 64), 256, QJ_BYTES>>>(fused_visual, q_w, q_b);
    attn_kernel<<<dim3(Nn / 128, NH, Bv), 256, AT_BYTES>>>();
    oproj_kernel<<<Bv * (Nn / 64), 256, OJ_BYTES>>>(o_w, o_b, out);
}